// round 1
// baseline (speedup 1.0000x reference)
#include <cuda_runtime.h>

#define NMAX 200000
#define EMAX 3200000
#define GMAX 1024
#define HID  64

// ---- scratch (static device globals; no runtime allocation) ----
__device__ int   g_cnt[NMAX];          // in-degree counts
__device__ int   g_rowptr[NMAX + 1];   // CSR row pointers (by dst)
__device__ int   g_cursor[NMAX];       // scatter cursors
__device__ int   g_csr[EMAX];          // src index per CSR slot
__device__ int   g_bsums[1024];        // scan block sums
__device__ int   g_gcnt[GMAX];         // nodes per graph
__device__ int   g_goff[GMAX];         // graph start offsets (batch is sorted)
__device__ float g_dinv[NMAX];         // deg^{-1/2} (incl. self loop)
__device__ float g_bufx[NMAX * HID];   // xs = dinv * (h @ W)
__device__ float g_bufa[NMAX * HID];   // aggregated raw sums S

// -------------------- setup kernels --------------------

__global__ void k_zero(int n) {
    int i = blockIdx.x * blockDim.x + threadIdx.x;
    if (i < n) g_cnt[i] = 0;
    if (i < GMAX) g_gcnt[i] = 0;
}

__global__ void k_degcount(const int* __restrict__ dst, int e) {
    int i = blockIdx.x * blockDim.x + threadIdx.x;
    if (i < e) atomicAdd(&g_cnt[dst[i]], 1);
}

__global__ void k_gcount(const int* __restrict__ batch, int n) {
    int i = blockIdx.x * blockDim.x + threadIdx.x;
    if (i < n) atomicAdd(&g_gcnt[batch[i]], 1);
}

// block-level exclusive scan of g_cnt; 1024 threads/block
__global__ void k_scanA(int n) {
    __shared__ int s[1024];
    int t = threadIdx.x;
    int i = blockIdx.x * 1024 + t;
    int v = (i < n) ? g_cnt[i] : 0;
    s[t] = v;
    __syncthreads();
    #pragma unroll
    for (int off = 1; off < 1024; off <<= 1) {
        int u = (t >= off) ? s[t - off] : 0;
        __syncthreads();
        s[t] += u;
        __syncthreads();
    }
    if (i < n) g_rowptr[i] = s[t] - v;            // local exclusive
    if (t == 1023) g_bsums[blockIdx.x] = s[1023]; // block total
}

// scan of block sums (nb <= 1024); also writes grand total to rowptr[n]
__global__ void k_scanB(int nb, int n) {
    __shared__ int s[1024];
    int t = threadIdx.x;
    int v = (t < nb) ? g_bsums[t] : 0;
    s[t] = v;
    __syncthreads();
    #pragma unroll
    for (int off = 1; off < 1024; off <<= 1) {
        int u = (t >= off) ? s[t - off] : 0;
        __syncthreads();
        s[t] += u;
        __syncthreads();
    }
    if (t < nb) g_bsums[t] = s[t] - v;   // exclusive
    if (t == 1023) g_rowptr[n] = s[1023];
}

__global__ void k_scanC(int n) {
    int i = blockIdx.x * blockDim.x + threadIdx.x;
    if (i < n) {
        int r = g_rowptr[i] + g_bsums[i >> 10];
        g_rowptr[i] = r;
        g_cursor[i] = r;
    }
}

__global__ void k_dinv(int n) {
    int i = blockIdx.x * blockDim.x + threadIdx.x;
    if (i < n) g_dinv[i] = rsqrtf((float)(g_cnt[i] + 1)); // +1 self loop
}

__global__ void k_fill(const int* __restrict__ src, const int* __restrict__ dst, int e) {
    int i = blockIdx.x * blockDim.x + threadIdx.x;
    if (i < e) {
        int d = dst[i];
        int p = atomicAdd(&g_cursor[d], 1);
        g_csr[p] = src[i];
    }
}

// exclusive scan of per-graph counts -> graph start offsets (batch is sorted)
__global__ void k_gscan() {
    __shared__ int s[GMAX];
    int t = threadIdx.x;
    int v = g_gcnt[t];
    s[t] = v;
    __syncthreads();
    #pragma unroll
    for (int off = 1; off < GMAX; off <<= 1) {
        int u = (t >= off) ? s[t - off] : 0;
        __syncthreads();
        s[t] += u;
        __syncthreads();
    }
    g_goff[t] = s[t] - v;
}

// -------------------- layer kernels --------------------

// layer 1 transform: xs[v] = dinv[v] * (x[v] @ W1)  (x is N x 9)
__global__ __launch_bounds__(256) void k_t1(const float* __restrict__ x,
                                            const float* __restrict__ W1, int n) {
    __shared__ float Ws[9 * 64];
    __shared__ float Xs[4][12];
    int tid = threadIdx.x;
    for (int i = tid; i < 9 * 64; i += 256) Ws[i] = W1[i];
    int base = blockIdx.x * 4;
    if (tid < 36) {
        int nl = tid / 9, k = tid % 9;
        int v = base + nl;
        Xs[nl][k] = (v < n) ? x[v * 9 + k] : 0.f;
    }
    __syncthreads();
    int nl = tid >> 6, f = tid & 63;
    int v = base + nl;
    if (v < n) {
        float a = 0.f;
        #pragma unroll
        for (int k = 0; k < 9; k++) a = fmaf(Xs[nl][k], Ws[k * 64 + f], a);
        g_bufx[v * 64 + f] = g_dinv[v] * a;
    }
}

// aggregation: bufa[v] = bufx[v] + sum over in-edges bufx[src]   (one warp/node)
__global__ __launch_bounds__(256) void k_gather(int n) {
    int w = (blockIdx.x * blockDim.x + threadIdx.x) >> 5;
    int lane = threadIdx.x & 31;
    if (w >= n) return;
    int beg = g_rowptr[w], end = g_rowptr[w + 1];
    int off = w * 64 + lane * 2;
    float ax = g_bufx[off], ay = g_bufx[off + 1];  // self-loop term
    int e = beg;
    for (; e + 4 <= end; e += 4) {
        int s0 = g_csr[e + 0], s1 = g_csr[e + 1];
        int s2 = g_csr[e + 2], s3 = g_csr[e + 3];
        float2 v0 = *(const float2*)&g_bufx[s0 * 64 + lane * 2];
        float2 v1 = *(const float2*)&g_bufx[s1 * 64 + lane * 2];
        float2 v2 = *(const float2*)&g_bufx[s2 * 64 + lane * 2];
        float2 v3 = *(const float2*)&g_bufx[s3 * 64 + lane * 2];
        ax += (v0.x + v1.x) + (v2.x + v3.x);
        ay += (v0.y + v1.y) + (v2.y + v3.y);
    }
    for (; e < end; e++) {
        int s = g_csr[e];
        float2 v = *(const float2*)&g_bufx[s * 64 + lane * 2];
        ax += v.x; ay += v.y;
    }
    *(float2*)&g_bufa[off] = make_float2(ax, ay);
}

// layers 2/3 transform: z = relu(dinv*S + b_prev); bufx = dinv * (z @ W)
// 256 threads, 64 nodes per block, 4x4 register tile per thread
__global__ __launch_bounds__(256) void k_tf(const float* __restrict__ W,
                                            const float* __restrict__ bias, int n) {
    __shared__ float Ws[64 * 64];
    __shared__ float Zs[64 * 65];
    int tid = threadIdx.x;
    int base = blockIdx.x * 64;
    for (int i = tid; i < 4096; i += 256) Ws[i] = W[i];
    for (int i = tid; i < 4096; i += 256) {
        int nl = i >> 6, f = i & 63;
        int v = base + nl;
        float z = 0.f;
        if (v < n) z = fmaxf(fmaf(g_dinv[v], g_bufa[v * 64 + f], bias[f]), 0.f);
        Zs[nl * 65 + f] = z;
    }
    __syncthreads();
    int fg = tid & 15, ng = tid >> 4;
    int f0 = fg * 4, n0 = ng * 4;
    float a[4][4] = {};
    #pragma unroll 4
    for (int k = 0; k < 64; k++) {
        float4 w = *(const float4*)&Ws[k * 64 + f0];
        float z0 = Zs[(n0 + 0) * 65 + k];
        float z1 = Zs[(n0 + 1) * 65 + k];
        float z2 = Zs[(n0 + 2) * 65 + k];
        float z3 = Zs[(n0 + 3) * 65 + k];
        a[0][0] = fmaf(z0, w.x, a[0][0]); a[0][1] = fmaf(z0, w.y, a[0][1]);
        a[0][2] = fmaf(z0, w.z, a[0][2]); a[0][3] = fmaf(z0, w.w, a[0][3]);
        a[1][0] = fmaf(z1, w.x, a[1][0]); a[1][1] = fmaf(z1, w.y, a[1][1]);
        a[1][2] = fmaf(z1, w.z, a[1][2]); a[1][3] = fmaf(z1, w.w, a[1][3]);
        a[2][0] = fmaf(z2, w.x, a[2][0]); a[2][1] = fmaf(z2, w.y, a[2][1]);
        a[2][2] = fmaf(z2, w.z, a[2][2]); a[2][3] = fmaf(z2, w.w, a[2][3]);
        a[3][0] = fmaf(z3, w.x, a[3][0]); a[3][1] = fmaf(z3, w.y, a[3][1]);
        a[3][2] = fmaf(z3, w.z, a[3][2]); a[3][3] = fmaf(z3, w.w, a[3][3]);
    }
    #pragma unroll
    for (int i = 0; i < 4; i++) {
        int v = base + n0 + i;
        if (v < n) {
            float dv = g_dinv[v];
            float4 r = make_float4(dv * a[i][0], dv * a[i][1], dv * a[i][2], dv * a[i][3]);
            *(float4*)&g_bufx[v * 64 + f0] = r;
        }
    }
}

// pooling + head: h3 = relu(dinv*S3 + b3); [mean|max] per graph; out = pooled@Wl + bl
__global__ __launch_bounds__(64) void k_pool(const float* __restrict__ b3,
                                             const float* __restrict__ Wl,
                                             const float* __restrict__ bl,
                                             float* __restrict__ outp) {
    int g = blockIdx.x, f = threadIdx.x;
    int beg = g_goff[g], cnt = g_gcnt[g];
    float bf = b3[f];
    float sum = 0.f, mx = 0.f;   // relu >= 0, so identity 0 is valid for nonempty graphs
    #pragma unroll 4
    for (int i = 0; i < cnt; i++) {
        int v = beg + i;
        float val = fmaxf(fmaf(g_dinv[v], g_bufa[v * 64 + f], bf), 0.f);
        sum += val;
        mx = fmaxf(mx, val);
    }
    __shared__ float pooled[128];
    pooled[f] = sum / fmaxf((float)cnt, 1.f);
    pooled[64 + f] = mx;
    __syncthreads();
    float o = bl[f];
    #pragma unroll 8
    for (int k = 0; k < 128; k++) o = fmaf(pooled[k], Wl[k * 64 + f], o);
    outp[g * 64 + f] = o;
}

// -------------------- launcher --------------------

extern "C" void kernel_launch(void* const* d_in, const int* in_sizes, int n_in,
                              void* d_out, int out_size) {
    const float* x     = (const float*)d_in[0];
    const int*   ei    = (const int*)  d_in[1];
    // d_in[2] = edge_attr (unused by reference)
    const int*   batch = (const int*)  d_in[3];
    const float* W1    = (const float*)d_in[4];
    const float* b1    = (const float*)d_in[5];
    const float* W2    = (const float*)d_in[6];
    const float* b2    = (const float*)d_in[7];
    const float* W3    = (const float*)d_in[8];
    const float* b3    = (const float*)d_in[9];
    const float* Wl    = (const float*)d_in[10];
    const float* bl    = (const float*)d_in[11];
    float* out = (float*)d_out;

    int n = in_sizes[0] / 9;   // nodes
    int e = in_sizes[1] / 2;   // edges
    const int* src = ei;
    const int* dst = ei + e;

    int gn  = (n + 255) / 256;
    int ge  = (e + 255) / 256;
    int nb  = (n + 1023) / 1024;

    // graph structure (identical across layers): degrees, CSR-by-dst, graph offsets
    k_zero<<<gn, 256>>>(n);
    k_degcount<<<ge, 256>>>(dst, e);
    k_gcount<<<gn, 256>>>(batch, n);
    k_scanA<<<nb, 1024>>>(n);
    k_scanB<<<1, 1024>>>(nb, n);
    k_scanC<<<gn, 256>>>(n);
    k_dinv<<<gn, 256>>>(n);
    k_fill<<<ge, 256>>>(src, dst, e);
    k_gscan<<<1, GMAX>>>();

    // layer 1
    k_t1<<<(n + 3) / 4, 256>>>(x, W1, n);
    k_gather<<<(n + 7) / 8, 256>>>(n);
    // layer 2
    k_tf<<<(n + 63) / 64, 256>>>(W2, b1, n);
    k_gather<<<(n + 7) / 8, 256>>>(n);
    // layer 3
    k_tf<<<(n + 63) / 64, 256>>>(W3, b2, n);
    k_gather<<<(n + 7) / 8, 256>>>(n);
    // pooling + linear head
    k_pool<<<GMAX, 64>>>(b3, Wl, bl, out);
}

// round 2
// speedup vs baseline: 1.1330x; 1.1330x over previous
#include <cuda_runtime.h>
#include <cuda_fp16.h>

#define NMAX 200000
#define EMAX 3200000
#define GMAX 1024

// ---- scratch (static device globals; no runtime allocation) ----
__device__ int     g_cnt[NMAX];
__device__ int     g_rowptr[NMAX + 1];
__device__ int     g_cursor[NMAX];
__device__ int     g_csr[EMAX];
__device__ int     g_bsums[1024];
__device__ int     g_gcnt[GMAX];
__device__ int     g_goff[GMAX];
__device__ float   g_dinv[NMAX];
__device__ float   g_xs9[NMAX * 9];    // dinv * x (9-dim, layer-1 messages)
__device__ float   g_agg9[NMAX * 9];   // layer-1 aggregated 9-dim sums
__device__ __half2 g_bufh[NMAX * 32];  // fp16 messages (64 feats as 32 half2)
__device__ float   g_bufa[NMAX * 64];  // fp32 aggregated sums

// packed fp32x2 FMA (FFMA2 — only reachable via PTX fma.rn.f32x2)
__device__ __forceinline__ unsigned long long ffma2(unsigned long long a,
                                                    unsigned long long b,
                                                    unsigned long long c) {
    unsigned long long d;
    asm("fma.rn.f32x2 %0, %1, %2, %3;" : "=l"(d) : "l"(a), "l"(b), "l"(c));
    return d;
}

// -------------------- setup kernels --------------------

__global__ void k_zero(int n) {
    int i = blockIdx.x * blockDim.x + threadIdx.x;
    if (i < n) g_cnt[i] = 0;
    if (i < GMAX) g_gcnt[i] = 0;
}

__global__ void k_count(const int* __restrict__ dst, const int* __restrict__ batch,
                        int n, int e) {
    int i = blockIdx.x * blockDim.x + threadIdx.x;
    if (i < e) atomicAdd(&g_cnt[dst[i]], 1);
    if (i < n) atomicAdd(&g_gcnt[batch[i]], 1);
}

__global__ void k_scanA(int n) {
    __shared__ int s[1024];
    int t = threadIdx.x;
    int i = blockIdx.x * 1024 + t;
    int v = (i < n) ? g_cnt[i] : 0;
    s[t] = v;
    __syncthreads();
    #pragma unroll
    for (int off = 1; off < 1024; off <<= 1) {
        int u = (t >= off) ? s[t - off] : 0;
        __syncthreads();
        s[t] += u;
        __syncthreads();
    }
    if (i < n) g_rowptr[i] = s[t] - v;
    if (t == 1023) g_bsums[blockIdx.x] = s[1023];
}

__global__ void k_scanB(int nb, int n) {
    __shared__ int s[1024];
    int t = threadIdx.x;
    int v = (t < nb) ? g_bsums[t] : 0;
    s[t] = v;
    __syncthreads();
    #pragma unroll
    for (int off = 1; off < 1024; off <<= 1) {
        int u = (t >= off) ? s[t - off] : 0;
        __syncthreads();
        s[t] += u;
        __syncthreads();
    }
    if (t < nb) g_bsums[t] = s[t] - v;
    if (t == 1023) g_rowptr[n] = s[1023];
}

// finalize rowptr/cursor + dinv + xs9 = dinv * x
__global__ void k_scanC(const float* __restrict__ x, int n) {
    int i = blockIdx.x * blockDim.x + threadIdx.x;
    if (i < n) {
        int r = g_rowptr[i] + g_bsums[i >> 10];
        g_rowptr[i] = r;
        g_cursor[i] = r;
        float dv = rsqrtf((float)(g_cnt[i] + 1));
        g_dinv[i] = dv;
        #pragma unroll
        for (int k = 0; k < 9; k++) g_xs9[i * 9 + k] = dv * x[i * 9 + k];
    }
}

__global__ void k_fill(const int* __restrict__ src, const int* __restrict__ dst, int e) {
    int i = blockIdx.x * blockDim.x + threadIdx.x;
    if (i < e) {
        int d = dst[i];
        int p = atomicAdd(&g_cursor[d], 1);
        g_csr[p] = src[i];
    }
}

__global__ void k_gscan() {
    __shared__ int s[GMAX];
    int t = threadIdx.x;
    int v = g_gcnt[t];
    s[t] = v;
    __syncthreads();
    #pragma unroll
    for (int off = 1; off < GMAX; off <<= 1) {
        int u = (t >= off) ? s[t - off] : 0;
        __syncthreads();
        s[t] += u;
        __syncthreads();
    }
    g_goff[t] = s[t] - v;
}

// -------------------- layer kernels --------------------

// layer-1 aggregation in 9-dim fp32: agg9[v] = xs9[v] + sum_in xs9[s]
__global__ __launch_bounds__(256) void k_gather9(int n) {
    int w = (blockIdx.x * blockDim.x + threadIdx.x) >> 5;
    int lane = threadIdx.x & 31;
    if (w >= n) return;
    int beg = g_rowptr[w], end = g_rowptr[w + 1];
    bool act = lane < 9;
    float acc = act ? g_xs9[w * 9 + lane] : 0.f;
    int e = beg;
    for (; e + 4 <= end; e += 4) {
        int s0 = __ldg(&g_csr[e + 0]), s1 = __ldg(&g_csr[e + 1]);
        int s2 = __ldg(&g_csr[e + 2]), s3 = __ldg(&g_csr[e + 3]);
        if (act) {
            float v0 = g_xs9[s0 * 9 + lane], v1 = g_xs9[s1 * 9 + lane];
            float v2 = g_xs9[s2 * 9 + lane], v3 = g_xs9[s3 * 9 + lane];
            acc += (v0 + v1) + (v2 + v3);
        }
    }
    for (; e < end; e++) {
        int s = __ldg(&g_csr[e]);
        if (act) acc += g_xs9[s * 9 + lane];
    }
    if (act) g_agg9[w * 9 + lane] = acc;
}

// shared FFMA2 GEMM mainloop + fp16 epilogue: bufh[v] = half(dinv_v * (Z[v] @ W))
// Zs2 holds z duplicated as (z,z) pairs; W read via __ldg (L1-resident, 16KB)
__device__ __forceinline__ void gemm_epi_h(const float2* Zs2, const float* __restrict__ W,
                                           int base, int n, int tid) {
    int fg = tid & 15, ng = tid >> 4;
    int f0 = fg * 4, n0 = ng * 4;
    unsigned long long acc[4][2] = {};
    const unsigned long long* Wq = reinterpret_cast<const unsigned long long*>(W);
    #pragma unroll 4
    for (int k = 0; k < 64; k++) {
        unsigned long long w01 = __ldg(&Wq[k * 32 + fg * 2]);
        unsigned long long w23 = __ldg(&Wq[k * 32 + fg * 2 + 1]);
        #pragma unroll
        for (int j = 0; j < 4; j++) {
            unsigned long long z =
                *reinterpret_cast<const unsigned long long*>(&Zs2[(n0 + j) * 64 + k]);
            acc[j][0] = ffma2(z, w01, acc[j][0]);
            acc[j][1] = ffma2(z, w23, acc[j][1]);
        }
    }
    #pragma unroll
    for (int j = 0; j < 4; j++) {
        int v = base + n0 + j;
        if (v < n) {
            float dv = g_dinv[v];
            float2 a0 = *reinterpret_cast<float2*>(&acc[j][0]);
            float2 a1 = *reinterpret_cast<float2*>(&acc[j][1]);
            __half2 h0 = __floats2half2_rn(dv * a0.x, dv * a0.y);
            __half2 h1 = __floats2half2_rn(dv * a1.x, dv * a1.y);
            uint2 u;
            u.x = *reinterpret_cast<unsigned*>(&h0);
            u.y = *reinterpret_cast<unsigned*>(&h1);
            *reinterpret_cast<uint2*>(&g_bufh[v * 32 + fg * 2]) = u;
        }
    }
}

// layer 1: z = relu(dinv*(agg9 @ W1) + b1); bufh = half(dinv * (z @ W2))
__global__ __launch_bounds__(256) void k_l1(const float* __restrict__ W1,
                                            const float* __restrict__ b1,
                                            const float* __restrict__ W2, int n) {
    __shared__ float W1s[9 * 64];
    __shared__ float A9s[64 * 9];
    __shared__ float dvs[64];
    __shared__ float b1s[64];
    __shared__ float2 Zs2[64 * 64];
    int tid = threadIdx.x;
    int base = blockIdx.x * 64;
    for (int i = tid; i < 576; i += 256) W1s[i] = W1[i];
    if (tid < 64) {
        int v = base + tid;
        dvs[tid] = (v < n) ? g_dinv[v] : 0.f;
        b1s[tid] = b1[tid];
    }
    for (int i = tid; i < 576; i += 256) {
        int nl = i / 9, k = i - nl * 9;
        int v = base + nl;
        A9s[i] = (v < n) ? g_agg9[v * 9 + k] : 0.f;
    }
    __syncthreads();
    for (int i = tid; i < 4096; i += 256) {
        int nl = i >> 6, f = i & 63;
        float s = 0.f;
        #pragma unroll
        for (int k = 0; k < 9; k++) s = fmaf(A9s[nl * 9 + k], W1s[k * 64 + f], s);
        float z = fmaxf(fmaf(dvs[nl], s, b1s[f]), 0.f);
        Zs2[nl * 64 + f] = make_float2(z, z);
    }
    __syncthreads();
    gemm_epi_h(Zs2, W2, base, n, tid);
}

// middle layer: z = relu(dinv*bufa + bias); bufh = half(dinv * (z @ W))
__global__ __launch_bounds__(256) void k_tf(const float* __restrict__ W,
                                            const float* __restrict__ bias, int n) {
    __shared__ float2 Zs2[64 * 64];
    __shared__ float b_s[64];
    __shared__ float dvs[64];
    int tid = threadIdx.x;
    int base = blockIdx.x * 64;
    if (tid < 64) {
        b_s[tid] = bias[tid];
        int v = base + tid;
        dvs[tid] = (v < n) ? g_dinv[v] : 0.f;
    }
    __syncthreads();
    for (int i = tid; i < 4096; i += 256) {
        int nl = i >> 6, f = i & 63;
        int v = base + nl;
        float z = 0.f;
        if (v < n) z = fmaxf(fmaf(dvs[nl], g_bufa[v * 64 + f], b_s[f]), 0.f);
        Zs2[nl * 64 + f] = make_float2(z, z);
    }
    __syncthreads();
    gemm_epi_h(Zs2, W, base, n, tid);
}

// fp16 aggregation: bufa[v] = bufh[v] + sum_in bufh[s]  (fp32 accumulate)
__global__ __launch_bounds__(256) void k_gather_h(int n) {
    int w = (blockIdx.x * blockDim.x + threadIdx.x) >> 5;
    int lane = threadIdx.x & 31;
    if (w >= n) return;
    int beg = g_rowptr[w], end = g_rowptr[w + 1];
    float2 hs = __half22float2(g_bufh[w * 32 + lane]);
    float ax = hs.x, ay = hs.y;
    int e = beg;
    for (; e + 8 <= end; e += 8) {
        int s[8];
        #pragma unroll
        for (int q = 0; q < 8; q++) s[q] = __ldg(&g_csr[e + q]);
        #pragma unroll
        for (int q = 0; q < 8; q++) {
            float2 v = __half22float2(__ldg(&g_bufh[s[q] * 32 + lane]));
            ax += v.x; ay += v.y;
        }
    }
    for (; e < end; e++) {
        int s = __ldg(&g_csr[e]);
        float2 v = __half22float2(__ldg(&g_bufh[s * 32 + lane]));
        ax += v.x; ay += v.y;
    }
    *reinterpret_cast<float2*>(&g_bufa[w * 64 + lane * 2]) = make_float2(ax, ay);
}

// pooling + head: h3 = relu(dinv*S3 + b3); [mean|max]; out = pooled@Wl + bl
__global__ __launch_bounds__(64) void k_pool(const float* __restrict__ b3,
                                             const float* __restrict__ Wl,
                                             const float* __restrict__ bl,
                                             float* __restrict__ outp) {
    int g = blockIdx.x, f = threadIdx.x;
    int beg = g_goff[g], cnt = g_gcnt[g];
    float bf = b3[f];
    float sum = 0.f, mx = 0.f;
    #pragma unroll 4
    for (int i = 0; i < cnt; i++) {
        int v = beg + i;
        float val = fmaxf(fmaf(g_dinv[v], g_bufa[v * 64 + f], bf), 0.f);
        sum += val;
        mx = fmaxf(mx, val);
    }
    __shared__ float pooled[128];
    pooled[f] = sum / fmaxf((float)cnt, 1.f);
    pooled[64 + f] = mx;
    __syncthreads();
    float o = bl[f];
    #pragma unroll 8
    for (int k = 0; k < 128; k++) o = fmaf(pooled[k], Wl[k * 64 + f], o);
    outp[g * 64 + f] = o;
}

// -------------------- launcher --------------------

extern "C" void kernel_launch(void* const* d_in, const int* in_sizes, int n_in,
                              void* d_out, int out_size) {
    const float* x     = (const float*)d_in[0];
    const int*   ei    = (const int*)  d_in[1];
    const int*   batch = (const int*)  d_in[3];
    const float* W1    = (const float*)d_in[4];
    const float* b1    = (const float*)d_in[5];
    const float* W2    = (const float*)d_in[6];
    const float* b2    = (const float*)d_in[7];
    const float* W3    = (const float*)d_in[8];
    const float* b3    = (const float*)d_in[9];
    const float* Wl    = (const float*)d_in[10];
    const float* bl    = (const float*)d_in[11];
    float* out = (float*)d_out;

    int n = in_sizes[0] / 9;
    int e = in_sizes[1] / 2;
    const int* src = ei;
    const int* dst = ei + e;

    int gn = (n + 255) / 256;
    int ge = (e + 255) / 256;
    int nb = (n + 1023) / 1024;

    // graph structure
    k_zero<<<gn, 256>>>(n);
    k_count<<<ge, 256>>>(dst, batch, n, e);
    k_scanA<<<nb, 1024>>>(n);
    k_scanB<<<1, 1024>>>(nb, n);
    k_scanC<<<gn, 256>>>(x, n);
    k_fill<<<ge, 256>>>(src, dst, e);
    k_gscan<<<1, GMAX>>>();

    // layer 1: aggregate raw 9-dim features (exact fp32), then both linears
    k_gather9<<<(n + 7) / 8, 256>>>(n);
    k_l1<<<(n + 63) / 64, 256>>>(W1, b1, W2, n);
    // layer 2
    k_gather_h<<<(n + 7) / 8, 256>>>(n);
    k_tf<<<(n + 63) / 64, 256>>>(W3, b2, n);
    // layer 3
    k_gather_h<<<(n + 7) / 8, 256>>>(n);
    // pooling + head
    k_pool<<<GMAX, 64>>>(b3, Wl, bl, out);
}